// round 13
// baseline (speedup 1.0000x reference)
#include <cuda_runtime.h>
#include <cuda_bf16.h>
#include <cstdint>

#define BB 64
#define SS 512
#define HH 768
#define LL 9

#define RB 128                    // rows per block (gemm)
#define NCHUNK 24                 // 768 / 32
#define B0_U32 (96 * 64)          // ntile0 frag table
#define B1_U32 (96 * 8)           // ntile1 compact (only n=8 real)
#define GEMM_SMEM_BYTES ((B0_U32 + B1_U32) * 4)   // 27648

__device__ float g_feats[(size_t)BB * SS * LL];
__device__ float g_part[BB];

__device__ __forceinline__ float ex2f_(float x) {
    float y; asm("ex2.approx.ftz.f32 %0, %1;" : "=f"(y) : "f"(x)); return y;
}
__device__ __forceinline__ float lg2f_(float x) {
    float y; asm("lg2.approx.f32 %0, %1;" : "=f"(y) : "f"(x)); return y;
}
__device__ __forceinline__ uint32_t f2tf32_(float v) {
    uint32_t t; asm("cvt.rna.tf32.f32 %0, %1;" : "=r"(t) : "f"(v)); return t;
}

// ---------------------------------------------------------------------------
// Kernel 1 (tensor): feats[m][l] = hidden[m][:].W[l][:] + b[l]
// tf32 mma.sync.m16n8k8, A loaded DIRECTLY into fragment registers via
// LDG.32 (no smem staging, no cp.async): lane (g,c) of warp w needs rows
// {w*16+g, w*16+g+8} x cols {s*8+c, s*8+c+4} of the current 32-k chunk =
// 16 floats = 16 LDG.32 warp-instrs per chunk (vs 128 LDGSTS before --
// removes the copy-issue floor that capped DRAM at ~4TB/s). Raw fp32 bits
// feed tf32 MMA (truncation, within tolerance). 3-deep register prefetch
// keeps 16 lines/warp in flight. B frag tables in smem (built once).
// Mainloop has ZERO barriers and zero smem traffic for A.
// ---------------------------------------------------------------------------
__global__ __launch_bounds__(256)
void gemm_kernel(const float* __restrict__ hidden,
                 const float* __restrict__ W,
                 const float* __restrict__ bias,
                 float* __restrict__ feats) {
    extern __shared__ uint32_t dynsm[];
    uint32_t* Bfr0 = dynsm;              // [96][64]
    uint32_t* Bfr1 = Bfr0 + B0_U32;      // [96][8]

    const int tid  = threadIdx.x;
    const int warp = tid >> 5;
    const int lane = tid & 31;
    const int g = lane >> 2;           // 0..7
    const int c = lane & 3;            // 0..3

    // ---- build B fragment tables (once per block) ----
    for (int i = tid; i < B0_U32; i += 256) {
        int half = i & 1;
        int ln   = (i >> 1) & 31;
        int s    = i >> 6;
        int n = ln >> 2;
        int k = s * 8 + (ln & 3) + half * 4;
        Bfr0[i] = f2tf32_(__ldg(&W[n * HH + k]));
    }
    for (int i = tid; i < B1_U32; i += 256) {
        int half = i & 1;
        int ln   = (i >> 1) & 3;
        int s    = i >> 3;
        int k = s * 8 + ln + half * 4;
        Bfr1[i] = f2tf32_(__ldg(&W[8 * HH + k]));
    }

    const int row0 = blockIdx.x * RB + warp * 16 + g;   // lane's even row
    // lane base pointers: include the +c column offset
    const float* pA0 = hidden + (size_t)row0 * HH + c;        // row g
    const float* pA1 = hidden + (size_t)(row0 + 8) * HH + c;  // row g+8

    // chunk loader: 16 LDG.32 into a register buffer
    // buf[s*4+{0,1,2,3}] = {rowg k, rowg+8 k, rowg k+4, rowg+8 k+4}, k=s*8
    auto loadchunk = [&](float* buf, int kc) {
        const float* q0 = pA0 + kc * 32;
        const float* q1 = pA1 + kc * 32;
#pragma unroll
        for (int s = 0; s < 4; ++s) {
            buf[s * 4 + 0] = __ldg(q0 + s * 8);
            buf[s * 4 + 1] = __ldg(q1 + s * 8);
            buf[s * 4 + 2] = __ldg(q0 + s * 8 + 4);
            buf[s * 4 + 3] = __ldg(q1 + s * 8 + 4);
        }
    };

    float acc[2][4];
#pragma unroll
    for (int nt = 0; nt < 2; ++nt)
#pragma unroll
        for (int j = 0; j < 4; ++j) acc[nt][j] = 0.f;

    float r0[16], r1[16], r2[16];
    loadchunk(r0, 0);
    loadchunk(r1, 1);
    loadchunk(r2, 2);

    __syncthreads();   // B tables ready

#pragma unroll 3
    for (int kc = 0; kc < NCHUNK; ++kc) {
        float cur[16];
#pragma unroll
        for (int j = 0; j < 16; ++j) cur[j] = r0[j];
#pragma unroll
        for (int j = 0; j < 16; ++j) r0[j] = r1[j];
#pragma unroll
        for (int j = 0; j < 16; ++j) r1[j] = r2[j];
        if (kc + 3 < NCHUNK) loadchunk(r2, kc + 3);

#pragma unroll
        for (int s = 0; s < 4; ++s) {
            uint32_t a0 = __float_as_uint(cur[s * 4 + 0]);
            uint32_t a1 = __float_as_uint(cur[s * 4 + 1]);
            uint32_t a2 = __float_as_uint(cur[s * 4 + 2]);
            uint32_t a3 = __float_as_uint(cur[s * 4 + 3]);
            int sg = kc * 4 + s;

            uint2 b0 = *reinterpret_cast<const uint2*>(Bfr0 + sg * 64 + lane * 2);
            asm volatile(
                "mma.sync.aligned.m16n8k8.row.col.f32.tf32.tf32.f32 "
                "{%0,%1,%2,%3}, {%4,%5,%6,%7}, {%8,%9}, {%0,%1,%2,%3};"
                : "+f"(acc[0][0]), "+f"(acc[0][1]),
                  "+f"(acc[0][2]), "+f"(acc[0][3])
                : "r"(a0), "r"(a1), "r"(a2), "r"(a3),
                  "r"(b0.x), "r"(b0.y));

            uint2 b1 = make_uint2(0u, 0u);
            if (lane < 4)
                b1 = *reinterpret_cast<const uint2*>(Bfr1 + sg * 8 + lane * 2);
            asm volatile(
                "mma.sync.aligned.m16n8k8.row.col.f32.tf32.tf32.f32 "
                "{%0,%1,%2,%3}, {%4,%5,%6,%7}, {%8,%9}, {%0,%1,%2,%3};"
                : "+f"(acc[1][0]), "+f"(acc[1][1]),
                  "+f"(acc[1][2]), "+f"(acc[1][3])
                : "r"(a0), "r"(a1), "r"(a2), "r"(a3),
                  "r"(b1.x), "r"(b1.y));
        }
    }

    // ---- epilogue: D frag (rows g/g+8, cols 2c,2c+1 per ntile) ----
    const int orow0 = row0;
    const int orow1 = row0 + 8;
#pragma unroll
    for (int nt = 0; nt < 2; ++nt) {
        int col0 = nt * 8 + 2 * c;
        int col1 = col0 + 1;
        if (col0 < LL) {
            float b0 = __ldg(&bias[col0]);
            feats[(size_t)orow0 * LL + col0] = acc[nt][0] + b0;
            feats[(size_t)orow1 * LL + col0] = acc[nt][2] + b0;
        }
        if (col1 < LL) {
            float b1 = __ldg(&bias[col1]);
            feats[(size_t)orow0 * LL + col1] = acc[nt][1] + b1;
            feats[(size_t)orow1 * LL + col1] = acc[nt][3] + b1;
        }
    }
}

// ---------------------------------------------------------------------------
// Kernel 2: one block (256 thr, 8 warps) per batch.  (unchanged, proven)
// Blocked parallel CRF scan: warp s computes the 9x9 linear-domain transfer
// matrix product over its 64-step segment; warp 0 chains alpha through the
// 8 matrices. Exact power-of-2 rescale every 8 steps.
// ---------------------------------------------------------------------------
__global__ __launch_bounds__(256, 1)
void crf_kernel(const float* __restrict__ feats,
                const float* __restrict__ start_tr,
                const float* __restrict__ end_tr,
                const float* __restrict__ trans,
                const int* __restrict__ labels,
                const unsigned char* __restrict__ mask8,
                float* __restrict__ partials) {
    __shared__ float sm_ef[SS * LL];
    __shared__ float sm_M[8][81];
    __shared__ float sm_C[8];
    __shared__ float sm_red[8];
    __shared__ float sm_score;
    __shared__ int   sm_len;

    const int b = blockIdx.x;
    const int tid = threadIdx.x;
    const int wid = tid >> 5;
    const int lane = tid & 31;
    const unsigned FULL = 0xffffffffu;
    const float LOG2E = 1.4426950408889634f;
    const float LN2   = 0.6931471805599453f;

    // ---- sequence length (mask monotone: mask[t] = t < len) ----
    const unsigned char* mrow = mask8 + (size_t)b * SS;
    int cnt = 0;
    for (int t = tid; t < SS; t += 256) cnt += (int)mrow[t];
    cnt = __reduce_add_sync(FULL, cnt);
    if (lane == 0) sm_red[wid] = (float)cnt;
    __syncthreads();
    if (tid == 0) {
        int l = 0;
        for (int w = 0; w < 8; w++) l += (int)sm_red[w];
        sm_len = l;
    }
    __syncthreads();
    int len = sm_len;
    if (len < SS / 2) {   // fallback: mask stored as int32 (lens >= 256 if u8)
        const int* mi = reinterpret_cast<const int*>(mask8) + (size_t)b * SS;
        cnt = 0;
        for (int t = tid; t < SS; t += 256) cnt += (mi[t] != 0);
        cnt = __reduce_add_sync(FULL, cnt);
        if (lane == 0) sm_red[wid] = (float)cnt;
        __syncthreads();
        if (tid == 0) {
            int l = 0;
            for (int w = 0; w < 8; w++) l += (int)sm_red[w];
            sm_len = l;
        }
        __syncthreads();
        len = sm_len;
    }
    __syncthreads();

    // ---- ef table: sm_ef[t*9+j] = exp(feats[b][t][j]) (vectorized) ----
    const float* frow = feats + (size_t)b * SS * LL;
    for (int i = tid; i < (SS * LL) / 4; i += 256) {
        float4 v = reinterpret_cast<const float4*>(frow)[i];
        float4 e;
        e.x = ex2f_(v.x * LOG2E); e.y = ex2f_(v.y * LOG2E);
        e.z = ex2f_(v.z * LOG2E); e.w = ex2f_(v.w * LOG2E);
        reinterpret_cast<float4*>(sm_ef)[i] = e;
    }

    // ---- gold path score (block-parallel over t) ----
    const int* lab = labels + (size_t)b * SS;
    float sc = 0.f;
    for (int t = tid; t < SS; t += 256) {
        int lt = lab[t];
        if (t == 0) {
            sc += __ldg(&start_tr[lt]) + frow[lt];
        } else if (t < len) {
            sc += __ldg(&trans[lab[t - 1] * LL + lt]) + frow[t * LL + lt];
        }
        if (t == len - 1) sc += __ldg(&end_tr[lt]);
    }
#pragma unroll
    for (int o = 16; o > 0; o >>= 1) sc += __shfl_xor_sync(FULL, sc, o);
    if (lane == 0) sm_red[wid] = sc;
    __syncthreads();
    if (tid == 0) {
        float s = 0.f;
        for (int w = 0; w < 8; w++) s += sm_red[w];
        sm_score = s;
    }

    // ---- per-warp segment matrix product ----
    const int a = (lane < 27) ? (lane / 3) : 8;
    const int g = lane % 3;
    float Ec[LL][3];
#pragma unroll
    for (int i = 0; i < LL; i++)
#pragma unroll
        for (int k = 0; k < 3; k++)
            Ec[i][k] = __expf(__ldg(&trans[i * LL + 3 * g + k]));

    float Mr[3];
#pragma unroll
    for (int k = 0; k < 3; k++) Mr[k] = (3 * g + k == a) ? 1.f : 0.f;
    float Cw = 0.f;

    __syncthreads();  // sm_ef ready

    const int t0 = max(1, wid * 64);
    const int t1 = min(len, (wid + 1) * 64);
    for (int t = t0; t < t1; ++t) {
        float ef0 = sm_ef[t * LL + 3 * g + 0];
        float ef1 = sm_ef[t * LL + 3 * g + 1];
        float ef2 = sm_ef[t * LL + 3 * g + 2];

        float m[LL];
#pragma unroll
        for (int i = 0; i < LL; i++)
            m[i] = __shfl_sync(FULL, Mr[i % 3], a * 3 + i / 3);

        float o0a = m[0] * Ec[0][0], o0b = m[1] * Ec[1][0];
        float o1a = m[0] * Ec[0][1], o1b = m[1] * Ec[1][1];
        float o2a = m[0] * Ec[0][2], o2b = m[1] * Ec[1][2];
#pragma unroll
        for (int i = 2; i < LL; i += 2) {
            o0a = fmaf(m[i], Ec[i][0], o0a);
            o1a = fmaf(m[i], Ec[i][1], o1a);
            o2a = fmaf(m[i], Ec[i][2], o2a);
            if (i + 1 < LL) {
                o0b = fmaf(m[i + 1], Ec[i + 1][0], o0b);
                o1b = fmaf(m[i + 1], Ec[i + 1][1], o1b);
                o2b = fmaf(m[i + 1], Ec[i + 1][2], o2b);
            }
        }
        Mr[0] = (o0a + o0b) * ef0;
        Mr[1] = (o1a + o1b) * ef1;
        Mr[2] = (o2a + o2b) * ef2;

        if ((t & 7) == 7) {
            float u = __shfl_sync(FULL, Mr[0], 0);
            int e = (__float_as_int(u) >> 23) & 255;
            float scale = __int_as_float((254 - e) << 23);
            Mr[0] *= scale; Mr[1] *= scale; Mr[2] *= scale;
            Cw += (float)(e - 127);
        }
    }
    if (lane < 27) {
#pragma unroll
        for (int k = 0; k < 3; k++) sm_M[wid][a * LL + 3 * g + k] = Mr[k];
    }
    if (lane == 0) sm_C[wid] = Cw;
    __syncthreads();

    // ---- warp 0: chain alpha through the 8 segment matrices ----
    if (wid == 0) {
        float al = (lane < LL) ? sm_ef[lane] * __expf(__ldg(&start_tr[lane])) : 0.f;
        float C = 0.f;
#pragma unroll 1
        for (int s = 0; s < 8; ++s) {
            float m[LL];
#pragma unroll
            for (int i = 0; i < LL; i++) m[i] = __shfl_sync(FULL, al, i);
            const int jj = (lane < LL) ? lane : 0;
            float sum = 0.f;
#pragma unroll
            for (int i = 0; i < LL; i++)
                sum = fmaf(m[i], sm_M[s][i * LL + jj], sum);
            al = (lane < LL) ? sum : 0.f;
            C += sm_C[s];
            float u = __shfl_sync(FULL, al, 0);
            int e = (__float_as_int(u) >> 23) & 255;
            float scale = __int_as_float((254 - e) << 23);
            al *= scale;
            C += (float)(e - 127);
        }
        float ev = (lane < LL) ? al * __expf(__ldg(&end_tr[lane])) : 0.f;
#pragma unroll
        for (int o = 16; o > 0; o >>= 1) ev += __shfl_xor_sync(FULL, ev, o);
        float logden = LN2 * (C + lg2f_(ev));
        if (lane == 0) partials[b] = logden - sm_score;
    }
}

// ---------------------------------------------------------------------------
// Kernel 3: mean over 64 per-batch NLLs
// ---------------------------------------------------------------------------
__global__ void finalize_kernel(const float* __restrict__ p, float* __restrict__ out) {
    int lane = threadIdx.x;  // 32 threads
    float v = p[lane] + p[lane + 32];
#pragma unroll
    for (int o = 16; o > 0; o >>= 1) v += __shfl_xor_sync(0xffffffffu, v, o);
    if (lane == 0) out[0] = v * (1.0f / BB);
}

// ---------------------------------------------------------------------------
extern "C" void kernel_launch(void* const* d_in, const int* in_sizes, int n_in,
                              void* d_out, int out_size) {
    const float* hidden  = (const float*)d_in[0];
    const float* W       = (const float*)d_in[1];
    const float* bias    = (const float*)d_in[2];
    const float* start_t = (const float*)d_in[3];
    const float* end_t   = (const float*)d_in[4];
    const float* trans   = (const float*)d_in[5];
    const int*   labels  = (const int*)d_in[6];
    const unsigned char* mask = (const unsigned char*)d_in[7];
    float* out = (float*)d_out;

    float* feats = nullptr;
    float* part  = nullptr;
    cudaGetSymbolAddress((void**)&feats, g_feats);
    cudaGetSymbolAddress((void**)&part,  g_part);

    gemm_kernel<<<256, 256, GEMM_SMEM_BYTES>>>(hidden, W, bias, feats);
    crf_kernel<<<BB, 256>>>(feats, start_t, end_t, trans, labels, mask, part);
    finalize_kernel<<<1, 32>>>(part, out);
}

// round 14
// speedup vs baseline: 1.3642x; 1.3642x over previous
#include <cuda_runtime.h>
#include <cuda_bf16.h>
#include <cstdint>

#define BB 64
#define SS 512
#define HH 768
#define LL 9

#define RB 128                    // rows per block (gemm)
#define NCHUNK 24                 // 768 / 32
#define WBUF_U32 576              // one warp-stage: 16 rows x 36 u32
#define AW_U32 (2 * WBUF_U32)     // per-warp double buffer
#define A_U32 (8 * AW_U32)        // 9216
#define B0_U32 (96 * 64)          // ntile0 frag table
#define B1_U32 (96 * 8)           // ntile1 compact (only n=8 real)
#define GEMM_SMEM_BYTES ((A_U32 + B0_U32 + B1_U32) * 4)   // 64512

__device__ float g_feats[(size_t)BB * SS * LL];
__device__ float g_part[BB];

__device__ __forceinline__ float ex2f_(float x) {
    float y; asm("ex2.approx.ftz.f32 %0, %1;" : "=f"(y) : "f"(x)); return y;
}
__device__ __forceinline__ float lg2f_(float x) {
    float y; asm("lg2.approx.f32 %0, %1;" : "=f"(y) : "f"(x)); return y;
}
__device__ __forceinline__ uint32_t f2tf32_(float v) {
    uint32_t t; asm("cvt.rna.tf32.f32 %0, %1;" : "=r"(t) : "f"(v)); return t;
}

// ---------------------------------------------------------------------------
// Kernel 1 (tensor): feats[m][l] = hidden[m][:].W[l][:] + b[l]
// tf32 mma.sync.m16n8k8, A raw fp32 bits (tf32 truncation, within tol).
// Per-warp barrier-free pipeline as in the 37.5us best, but the copy engine
// is LDG.128 + STS.128 through registers instead of 128x cp.async(16B):
// per warp-chunk 4 LDG.128 (4 lines each, coalesced) + 4 STS.128 + 16 frag
// LDS.32 (stride-36 smem -> all conflict-free) = 24 LSU ops vs 128 -> the
// LDGSTS issue floor that capped DRAM at ~4TB/s is gone. Two register
// buffers (rA/rB): an LDG is consumed by its STS two chunks later; loop
// unrolled x2 so buffer names are static. One __syncwarp per chunk, no
// block barriers in the mainloop.
// ---------------------------------------------------------------------------
__global__ __launch_bounds__(256)
void gemm_kernel(const float* __restrict__ hidden,
                 const float* __restrict__ W,
                 const float* __restrict__ bias,
                 float* __restrict__ feats) {
    extern __shared__ uint32_t dynsm[];
    uint32_t* Bfr0 = dynsm + A_U32;      // [96][64]
    uint32_t* Bfr1 = Bfr0 + B0_U32;      // [96][8]

    const int tid  = threadIdx.x;
    const int warp = tid >> 5;
    const int lane = tid & 31;
    const int g = lane >> 2;           // 0..7
    const int c = lane & 3;            // 0..3

    // ---- build B fragment tables (once per block) ----
    for (int i = tid; i < B0_U32; i += 256) {
        int half = i & 1;
        int ln   = (i >> 1) & 31;
        int s    = i >> 6;
        int n = ln >> 2;
        int k = s * 8 + (ln & 3) + half * 4;
        Bfr0[i] = f2tf32_(__ldg(&W[n * HH + k]));
    }
    for (int i = tid; i < B1_U32; i += 256) {
        int half = i & 1;
        int ln   = (i >> 1) & 3;
        int s    = i >> 3;
        int k = s * 8 + ln + half * 4;
        Bfr1[i] = f2tf32_(__ldg(&W[8 * HH + k]));
    }

    const int rowbase = blockIdx.x * RB + warp * 16;
    uint32_t* Aw = dynsm + warp * AW_U32;    // [2][576]

    // lane's copy slots: 4 x (row r, seg) with r = (lane+32j)>>3, seg = lane&7
    const int seg = lane & 7;
    const int rr  = lane >> 3;               // 0..3; rows rr, rr+4, rr+8, rr+12

    // LDG.128: chunk kc -> 4 float4 in regs
    auto ldgchunk = [&](float4* r, int kc) {
#pragma unroll
        for (int j = 0; j < 4; ++j) {
            r[j] = *reinterpret_cast<const float4*>(
                hidden + (size_t)(rowbase + rr + 4 * j) * HH + kc * 32 + seg * 4);
        }
    };
    // STS.128 into warp buffer st
    auto stschunk = [&](const float4* r, int st) {
        uint32_t* dst = Aw + st * WBUF_U32;
#pragma unroll
        for (int j = 0; j < 4; ++j) {
            *reinterpret_cast<float4*>(dst + (rr + 4 * j) * 36 + seg * 4) = r[j];
        }
    };

    float acc[2][4];
#pragma unroll
    for (int nt = 0; nt < 2; ++nt)
#pragma unroll
        for (int j = 0; j < 4; ++j) acc[nt][j] = 0.f;

    // fragment LDS + 8 MMA for one chunk
    auto compute = [&](int st, int kc) {
        const uint32_t* As = Aw + st * WBUF_U32;
#pragma unroll
        for (int s = 0; s < 4; ++s) {
            const uint32_t* a0p = As + g * 36 + s * 8 + c;
            uint32_t a0 = a0p[0];
            uint32_t a2 = a0p[4];
            uint32_t a1 = a0p[8 * 36];
            uint32_t a3 = a0p[8 * 36 + 4];
            int sg = kc * 4 + s;

            uint2 b0 = *reinterpret_cast<const uint2*>(Bfr0 + sg * 64 + lane * 2);
            asm volatile(
                "mma.sync.aligned.m16n8k8.row.col.f32.tf32.tf32.f32 "
                "{%0,%1,%2,%3}, {%4,%5,%6,%7}, {%8,%9}, {%0,%1,%2,%3};"
                : "+f"(acc[0][0]), "+f"(acc[0][1]),
                  "+f"(acc[0][2]), "+f"(acc[0][3])
                : "r"(a0), "r"(a1), "r"(a2), "r"(a3),
                  "r"(b0.x), "r"(b0.y));

            uint2 b1 = make_uint2(0u, 0u);
            if (lane < 4)
                b1 = *reinterpret_cast<const uint2*>(Bfr1 + sg * 8 + lane * 2);
            asm volatile(
                "mma.sync.aligned.m16n8k8.row.col.f32.tf32.tf32.f32 "
                "{%0,%1,%2,%3}, {%4,%5,%6,%7}, {%8,%9}, {%0,%1,%2,%3};"
                : "+f"(acc[1][0]), "+f"(acc[1][1]),
                  "+f"(acc[1][2]), "+f"(acc[1][3])
                : "r"(a0), "r"(a1), "r"(a2), "r"(a3),
                  "r"(b1.x), "r"(b1.y));
        }
    };

    float4 rA[4], rB[4];

    // prologue: rA=c0, rB=c1; buf0 <- c0; rA reloaded with c2
    ldgchunk(rA, 0);
    ldgchunk(rB, 1);
    stschunk(rA, 0);
    ldgchunk(rA, 2);
    __syncthreads();   // B tables ready + buf0 visible warp-wide

    // invariant at top of iter kc (kc even): buf[0]=c(kc) ready,
    // rB=c(kc+1), rA=c(kc+2)
#pragma unroll 1
    for (int kc = 0; kc < NCHUNK; kc += 2) {
        // even body: chunk kc from buf0
        stschunk(rB, 1);                      // c(kc+1) -> buf1
        if (kc + 3 < NCHUNK) ldgchunk(rB, kc + 3);
        compute(0, kc);
        __syncwarp();

        // odd body: chunk kc+1 from buf1
        if (kc + 2 < NCHUNK) stschunk(rA, 0); // c(kc+2) -> buf0
        if (kc + 4 < NCHUNK) ldgchunk(rA, kc + 4);
        compute(1, kc + 1);
        __syncwarp();
    }

    // ---- epilogue: D frag (rows g/g+8, cols 2c,2c+1 per ntile) ----
    const int row0 = rowbase + g;
    const int row1 = row0 + 8;
#pragma unroll
    for (int nt = 0; nt < 2; ++nt) {
        int col0 = nt * 8 + 2 * c;
        int col1 = col0 + 1;
        if (col0 < LL) {
            float b0 = __ldg(&bias[col0]);
            feats[(size_t)row0 * LL + col0] = acc[nt][0] + b0;
            feats[(size_t)row1 * LL + col0] = acc[nt][2] + b0;
        }
        if (col1 < LL) {
            float b1 = __ldg(&bias[col1]);
            feats[(size_t)row0 * LL + col1] = acc[nt][1] + b1;
            feats[(size_t)row1 * LL + col1] = acc[nt][3] + b1;
        }
    }
}

// ---------------------------------------------------------------------------
// Kernel 2: one block (256 thr, 8 warps) per batch.  (unchanged, proven)
// Blocked parallel CRF scan: warp s computes the 9x9 linear-domain transfer
// matrix product over its 64-step segment; warp 0 chains alpha through the
// 8 matrices. Exact power-of-2 rescale every 8 steps.
// ---------------------------------------------------------------------------
__global__ __launch_bounds__(256, 1)
void crf_kernel(const float* __restrict__ feats,
                const float* __restrict__ start_tr,
                const float* __restrict__ end_tr,
                const float* __restrict__ trans,
                const int* __restrict__ labels,
                const unsigned char* __restrict__ mask8,
                float* __restrict__ partials) {
    __shared__ float sm_ef[SS * LL];
    __shared__ float sm_M[8][81];
    __shared__ float sm_C[8];
    __shared__ float sm_red[8];
    __shared__ float sm_score;
    __shared__ int   sm_len;

    const int b = blockIdx.x;
    const int tid = threadIdx.x;
    const int wid = tid >> 5;
    const int lane = tid & 31;
    const unsigned FULL = 0xffffffffu;
    const float LOG2E = 1.4426950408889634f;
    const float LN2   = 0.6931471805599453f;

    // ---- sequence length (mask monotone: mask[t] = t < len) ----
    const unsigned char* mrow = mask8 + (size_t)b * SS;
    int cnt = 0;
    for (int t = tid; t < SS; t += 256) cnt += (int)mrow[t];
    cnt = __reduce_add_sync(FULL, cnt);
    if (lane == 0) sm_red[wid] = (float)cnt;
    __syncthreads();
    if (tid == 0) {
        int l = 0;
        for (int w = 0; w < 8; w++) l += (int)sm_red[w];
        sm_len = l;
    }
    __syncthreads();
    int len = sm_len;
    if (len < SS / 2) {   // fallback: mask stored as int32 (lens >= 256 if u8)
        const int* mi = reinterpret_cast<const int*>(mask8) + (size_t)b * SS;
        cnt = 0;
        for (int t = tid; t < SS; t += 256) cnt += (mi[t] != 0);
        cnt = __reduce_add_sync(FULL, cnt);
        if (lane == 0) sm_red[wid] = (float)cnt;
        __syncthreads();
        if (tid == 0) {
            int l = 0;
            for (int w = 0; w < 8; w++) l += (int)sm_red[w];
            sm_len = l;
        }
        __syncthreads();
        len = sm_len;
    }
    __syncthreads();

    // ---- ef table: sm_ef[t*9+j] = exp(feats[b][t][j]) (vectorized) ----
    const float* frow = feats + (size_t)b * SS * LL;
    for (int i = tid; i < (SS * LL) / 4; i += 256) {
        float4 v = reinterpret_cast<const float4*>(frow)[i];
        float4 e;
        e.x = ex2f_(v.x * LOG2E); e.y = ex2f_(v.y * LOG2E);
        e.z = ex2f_(v.z * LOG2E); e.w = ex2f_(v.w * LOG2E);
        reinterpret_cast<float4*>(sm_ef)[i] = e;
    }

    // ---- gold path score (block-parallel over t) ----
    const int* lab = labels + (size_t)b * SS;
    float sc = 0.f;
    for (int t = tid; t < SS; t += 256) {
        int lt = lab[t];
        if (t == 0) {
            sc += __ldg(&start_tr[lt]) + frow[lt];
        } else if (t < len) {
            sc += __ldg(&trans[lab[t - 1] * LL + lt]) + frow[t * LL + lt];
        }
        if (t == len - 1) sc += __ldg(&end_tr[lt]);
    }
#pragma unroll
    for (int o = 16; o > 0; o >>= 1) sc += __shfl_xor_sync(FULL, sc, o);
    if (lane == 0) sm_red[wid] = sc;
    __syncthreads();
    if (tid == 0) {
        float s = 0.f;
        for (int w = 0; w < 8; w++) s += sm_red[w];
        sm_score = s;
    }

    // ---- per-warp segment matrix product ----
    const int a = (lane < 27) ? (lane / 3) : 8;
    const int g = lane % 3;
    float Ec[LL][3];
#pragma unroll
    for (int i = 0; i < LL; i++)
#pragma unroll
        for (int k = 0; k < 3; k++)
            Ec[i][k] = __expf(__ldg(&trans[i * LL + 3 * g + k]));

    float Mr[3];
#pragma unroll
    for (int k = 0; k < 3; k++) Mr[k] = (3 * g + k == a) ? 1.f : 0.f;
    float Cw = 0.f;

    __syncthreads();  // sm_ef ready

    const int t0 = max(1, wid * 64);
    const int t1 = min(len, (wid + 1) * 64);
    for (int t = t0; t < t1; ++t) {
        float ef0 = sm_ef[t * LL + 3 * g + 0];
        float ef1 = sm_ef[t * LL + 3 * g + 1];
        float ef2 = sm_ef[t * LL + 3 * g + 2];

        float m[LL];
#pragma unroll
        for (int i = 0; i < LL; i++)
            m[i] = __shfl_sync(FULL, Mr[i % 3], a * 3 + i / 3);

        float o0a = m[0] * Ec[0][0], o0b = m[1] * Ec[1][0];
        float o1a = m[0] * Ec[0][1], o1b = m[1] * Ec[1][1];
        float o2a = m[0] * Ec[0][2], o2b = m[1] * Ec[1][2];
#pragma unroll
        for (int i = 2; i < LL; i += 2) {
            o0a = fmaf(m[i], Ec[i][0], o0a);
            o1a = fmaf(m[i], Ec[i][1], o1a);
            o2a = fmaf(m[i], Ec[i][2], o2a);
            if (i + 1 < LL) {
                o0b = fmaf(m[i + 1], Ec[i + 1][0], o0b);
                o1b = fmaf(m[i + 1], Ec[i + 1][1], o1b);
                o2b = fmaf(m[i + 1], Ec[i + 1][2], o2b);
            }
        }
        Mr[0] = (o0a + o0b) * ef0;
        Mr[1] = (o1a + o1b) * ef1;
        Mr[2] = (o2a + o2b) * ef2;

        if ((t & 7) == 7) {
            float u = __shfl_sync(FULL, Mr[0], 0);
            int e = (__float_as_int(u) >> 23) & 255;
            float scale = __int_as_float((254 - e) << 23);
            Mr[0] *= scale; Mr[1] *= scale; Mr[2] *= scale;
            Cw += (float)(e - 127);
        }
    }
    if (lane < 27) {
#pragma unroll
        for (int k = 0; k < 3; k++) sm_M[wid][a * LL + 3 * g + k] = Mr[k];
    }
    if (lane == 0) sm_C[wid] = Cw;
    __syncthreads();

    // ---- warp 0: chain alpha through the 8 segment matrices ----
    if (wid == 0) {
        float al = (lane < LL) ? sm_ef[lane] * __expf(__ldg(&start_tr[lane])) : 0.f;
        float C = 0.f;
#pragma unroll 1
        for (int s = 0; s < 8; ++s) {
            float m[LL];
#pragma unroll
            for (int i = 0; i < LL; i++) m[i] = __shfl_sync(FULL, al, i);
            const int jj = (lane < LL) ? lane : 0;
            float sum = 0.f;
#pragma unroll
            for (int i = 0; i < LL; i++)
                sum = fmaf(m[i], sm_M[s][i * LL + jj], sum);
            al = (lane < LL) ? sum : 0.f;
            C += sm_C[s];
            float u = __shfl_sync(FULL, al, 0);
            int e = (__float_as_int(u) >> 23) & 255;
            float scale = __int_as_float((254 - e) << 23);
            al *= scale;
            C += (float)(e - 127);
        }
        float ev = (lane < LL) ? al * __expf(__ldg(&end_tr[lane])) : 0.f;
#pragma unroll
        for (int o = 16; o > 0; o >>= 1) ev += __shfl_xor_sync(FULL, ev, o);
        float logden = LN2 * (C + lg2f_(ev));
        if (lane == 0) partials[b] = logden - sm_score;
    }
}

// ---------------------------------------------------------------------------
// Kernel 3: mean over 64 per-batch NLLs
// ---------------------------------------------------------------------------
__global__ void finalize_kernel(const float* __restrict__ p, float* __restrict__ out) {
    int lane = threadIdx.x;  // 32 threads
    float v = p[lane] + p[lane + 32];
#pragma unroll
    for (int o = 16; o > 0; o >>= 1) v += __shfl_xor_sync(0xffffffffu, v, o);
    if (lane == 0) out[0] = v * (1.0f / BB);
}

// ---------------------------------------------------------------------------
extern "C" void kernel_launch(void* const* d_in, const int* in_sizes, int n_in,
                              void* d_out, int out_size) {
    const float* hidden  = (const float*)d_in[0];
    const float* W       = (const float*)d_in[1];
    const float* bias    = (const float*)d_in[2];
    const float* start_t = (const float*)d_in[3];
    const float* end_t   = (const float*)d_in[4];
    const float* trans   = (const float*)d_in[5];
    const int*   labels  = (const int*)d_in[6];
    const unsigned char* mask = (const unsigned char*)d_in[7];
    float* out = (float*)d_out;

    float* feats = nullptr;
    float* part  = nullptr;
    cudaGetSymbolAddress((void**)&feats, g_feats);
    cudaGetSymbolAddress((void**)&part,  g_part);

    static bool attr_set = false;
    if (!attr_set) {
        cudaFuncSetAttribute(gemm_kernel,
                             cudaFuncAttributeMaxDynamicSharedMemorySize,
                             GEMM_SMEM_BYTES);
        attr_set = true;
    }

    gemm_kernel<<<256, 256, GEMM_SMEM_BYTES>>>(hidden, W, bias, feats);
    crf_kernel<<<BB, 256>>>(feats, start_t, end_t, trans, labels, mask, part);
    finalize_kernel<<<1, 32>>>(part, out);
}